// round 4
// baseline (speedup 1.0000x reference)
#include <cuda_runtime.h>

#define TPB 256
#define RPT 8                      // rows per thread (4 packed pairs)
#define NPAIR (RPT / 2)
#define HID 64
#define BETA_C 0.99f
#define EPS_V 1e-3f
#define LOG_2PI 1.8378770664093453f
#define LOG2E 1.4426950408889634f
#define GRID 1024                  // B / (TPB*RPT) = 2097152 / 2048

__device__ float g_part[GRID];
__device__ unsigned int g_count;   // zero-init; last block resets to 0

typedef unsigned long long ull;

__device__ __forceinline__ ull pk2(float lo, float hi) {
    ull r; asm("mov.b64 %0, {%1,%2};" : "=l"(r) : "f"(lo), "f"(hi)); return r;
}
__device__ __forceinline__ void upk2(float& lo, float& hi, ull v) {
    asm("mov.b64 {%0,%1}, %2;" : "=f"(lo), "=f"(hi) : "l"(v));
}
__device__ __forceinline__ ull fma2(ull a, ull b, ull c) {
    ull d; asm("fma.rn.f32x2 %0, %1, %2, %3;" : "=l"(d) : "l"(a), "l"(b), "l"(c)); return d;
}

__global__ __launch_bounds__(TPB) void mdn_main(
    const float* __restrict__ x, const float* __restrict__ y,
    const float* __restrict__ eps,
    const float* __restrict__ W1, const float* __restrict__ b1,
    const float* __restrict__ W2, const float* __restrict__ b2,
    const float* __restrict__ Wv,
    float* __restrict__ out, int B)
{
    // All weight scalars pre-duplicated into both f32x2 lanes.
    __shared__ ulonglong2 sH[HID];   // (.x = (w0j,w0j), .y = (w1j,w1j))
    __shared__ ull        sB[HID];   // (bj,bj)
    __shared__ ulonglong2 sW01[HID]; // (.x = dup W2[j][0], .y = dup W2[j][1])
    __shared__ ulonglong2 sW23[HID];

    int tid = threadIdx.x;
    if (tid < HID) {
        float w0 = W1[tid], w1 = W1[HID + tid], bb = b1[tid];
        float4 w2 = *reinterpret_cast<const float4*>(W2 + 4 * tid);
        reinterpret_cast<float4*>(&sH[tid])[0]   = make_float4(w0, w0, w1, w1);
        reinterpret_cast<float2*>(&sB[tid])[0]   = make_float2(bb, bb);
        reinterpret_cast<float4*>(&sW01[tid])[0] = make_float4(w2.x, w2.x, w2.y, w2.y);
        reinterpret_cast<float4*>(&sW23[tid])[0] = make_float4(w2.z, w2.z, w2.w, w2.w);
    }
    __syncthreads();

    const float v00 = __ldg(Wv + 0), v01 = __ldg(Wv + 1);
    const float v10 = __ldg(Wv + 2), v11 = __ldg(Wv + 3);
    const float c0 = __ldg(b2 + 0), c1 = __ldg(b2 + 1);
    const float c2 = __ldg(b2 + 2), c3 = __ldg(b2 + 3);

    const int nth = GRID * TPB;
    const int g   = blockIdx.x * TPB + tid;

    ull xp0[NPAIR], xp1[NPAIR];          // packed (x0 of row 2p, row 2p+1), ditto x1
    ull a0[NPAIR], a1[NPAIR], a2[NPAIR], a3[NPAIR];

    #pragma unroll
    for (int p = 0; p < NPAIR; p++) {
        int r0 = g + (2 * p)     * nth;
        int r1 = g + (2 * p + 1) * nth;
        float2 xa = *reinterpret_cast<const float2*>(x + 2 * r0);
        float2 xb = *reinterpret_cast<const float2*>(x + 2 * r1);
        xp0[p] = pk2(xa.x, xb.x);
        xp1[p] = pk2(xa.y, xb.y);
        a0[p] = pk2(c0, c0); a1[p] = pk2(c1, c1);
        a2[p] = pk2(c2, c2); a3[p] = pk2(c3, c3);
    }

    #pragma unroll 4
    for (int j = 0; j < HID; j++) {
        ulonglong2 Ad  = sH[j];
        ull        Bd  = sB[j];
        ulonglong2 W01 = sW01[j];
        ulonglong2 W23 = sW23[j];
        #pragma unroll
        for (int p = 0; p < NPAIR; p++) {
            ull h = fma2(Ad.x, xp0[p], fma2(Ad.y, xp1[p], Bd));
            float h0, h1; upk2(h0, h1, h);
            h0 = fmaxf(h0, 0.0f); h1 = fmaxf(h1, 0.0f);   // relu -> alu pipe
            h = pk2(h0, h1);
            a0[p] = fma2(W01.x, h, a0[p]);
            a1[p] = fma2(W01.y, h, a1[p]);
            a2[p] = fma2(W23.x, h, a2[p]);
            a3[p] = fma2(W23.y, h, a3[p]);
        }
    }

    float tsum = 0.0f;
    #pragma unroll
    for (int p = 0; p < NPAIR; p++) {
        float mu0a, mu0b, mu1a, mu1b, h2a, h2b, h3a, h3b;
        float x0a, x0b, x1a, x1b;
        upk2(mu0a, mu0b, a0[p]); upk2(mu1a, mu1b, a1[p]);
        upk2(h2a,  h2b,  a2[p]); upk2(h3a,  h3b,  a3[p]);
        upk2(x0a,  x0b,  xp0[p]); upk2(x1a,  x1b,  xp1[p]);

        #pragma unroll
        for (int q = 0; q < 2; q++) {
            int r = g + (2 * p + q) * nth;
            float mu0 = q ? mu0b : mu0a, mu1 = q ? mu1b : mu1a;
            float h2  = q ? h2b  : h2a,  h3  = q ? h3b  : h3a;
            float x0  = q ? x0b  : x0a,  x1  = q ? x1b  : x1a;

            float xa = fmaf(x0, v00, x1 * v10);
            float xb = fmaf(x0, v01, x1 * v11);
            float Vx = fmaf(xa, xa, fmaf(xb, xb, EPS_V));
            float ma = fmaf(mu0, v00, mu1 * v10);
            float mb = fmaf(mu0, v01, mu1 * v11);
            float Vmu = fmaf(ma, ma, fmaf(mb, mb, EPS_V));

            // (b*Vx - relu(b*Vx - Vmu)) / Vmu == min(b*Vx/Vmu, 1)
            float s = fminf(__fdividef(BETA_C * Vx, Vmu), 1.0f);
            float ms0 = mu0 * s, ms1 = mu1 * s;

            float sd0 = exp2f(h2 * (0.5f * LOG2E));
            float sd1 = exp2f(h3 * (0.5f * LOG2E));
            float iv0 = exp2f(h2 * (-LOG2E));
            float iv1 = exp2f(h3 * (-LOG2E));

            float2 ev = *reinterpret_cast<const float2*>(eps + 2 * r);
            float2 yv = *reinterpret_cast<const float2*>(y + 2 * r);

            float2 fx;
            fx.x = fmaf(sd0, ev.x, ms0);
            fx.y = fmaf(sd1, ev.y, ms1);
            *reinterpret_cast<float2*>(out + 2 * r) = fx;

            float d0 = yv.x - ms0, d1 = yv.y - ms1;
            tsum += fmaf(d0 * d0, iv0, fmaf(d1 * d1, iv1, h2 + h3));
        }
    }

    // intra-block reduction
    #pragma unroll
    for (int o = 16; o > 0; o >>= 1)
        tsum += __shfl_down_sync(0xFFFFFFFFu, tsum, o);

    __shared__ float wsum[TPB / 32];
    if ((tid & 31) == 0) wsum[tid >> 5] = tsum;
    __syncthreads();

    __shared__ bool s_last;
    if (tid == 0) {
        float bs = 0.0f;
        #pragma unroll
        for (int w = 0; w < TPB / 32; w++) bs += wsum[w];
        g_part[blockIdx.x] = bs;
        __threadfence();
        unsigned int old = atomicAdd(&g_count, 1u);
        s_last = (old == GRID - 1);
    }
    __syncthreads();

    // last arriving block: deterministic fixed-order final reduce
    if (s_last) {
        __shared__ float red[TPB];
        float s = 0.0f;
        for (int i = tid; i < GRID; i += TPB) s += g_part[i];
        red[tid] = s;
        __syncthreads();
        #pragma unroll
        for (int o = TPB / 2; o > 0; o >>= 1) {
            if (tid < o) red[tid] += red[tid + o];
            __syncthreads();
        }
        if (tid == 0) {
            out[(size_t)2 * (size_t)B] = fmaf(0.5f, red[0], (float)B * LOG_2PI);
            g_count = 0;   // reset for next graph replay
        }
    }
}

extern "C" void kernel_launch(void* const* d_in, const int* in_sizes, int n_in,
                              void* d_out, int out_size)
{
    const float* x   = (const float*)d_in[0];
    const float* y   = (const float*)d_in[1];
    const float* eps = (const float*)d_in[2];
    const float* W1  = (const float*)d_in[3];
    const float* b1  = (const float*)d_in[4];
    const float* W2  = (const float*)d_in[5];
    const float* b2  = (const float*)d_in[6];
    const float* Wv  = (const float*)d_in[7];
    float* out = (float*)d_out;

    int B = in_sizes[0] / 2;   // 2,097,152
    mdn_main<<<GRID, TPB>>>(x, y, eps, W1, b1, W2, b2, Wv, out, B);
}